// round 8
// baseline (speedup 1.0000x reference)
#include <cuda_runtime.h>
#include <stdint.h>

// StridedSlice: out[n,c,h,w] = x[n,c,2h,2w]
//   in : (8,128,512,512) f32   in row = 128 float4, plane = 65536 float4
//   out: (8,128,256,256) f32   out row = 64 float4, 262144 rows total
//
// One warp -> 4 consecutive output rows, symmetric 256-bit accesses.
// Per row: lane t stores out float4 [2t,2t+1] via one STG.256 (warp covers
// the full 1 KB row contiguously), sourced from in float4 [4t..4t+3] via
// two LDG.256 at 64 B lane stride (pair fully covers the 2 KB span).
// Processed as two row-pair halves to bound register liveness.

__device__ __forceinline__ void ldg256(const float4* __restrict__ p,
                                       float4& v0, float4& v1)
{
    asm("ld.global.v8.f32 {%0,%1,%2,%3,%4,%5,%6,%7}, [%8];"
        : "=f"(v0.x), "=f"(v0.y), "=f"(v0.z), "=f"(v0.w),
          "=f"(v1.x), "=f"(v1.y), "=f"(v1.z), "=f"(v1.w)
        : "l"(p));
}

__device__ __forceinline__ void stg256(float4* __restrict__ p,
                                       float a, float b, float c, float d,
                                       float e, float f, float g, float h)
{
    asm volatile("st.global.v8.f32 [%0], {%1,%2,%3,%4,%5,%6,%7,%8};"
                 :: "l"(p), "f"(a), "f"(b), "f"(c), "f"(d),
                    "f"(e), "f"(f), "f"(g), "f"(h)
                 : "memory");
}

__global__ __launch_bounds__(256) void strided_slice_kernel(
    const float4* __restrict__ in, float4* __restrict__ out)
{
    unsigned wg = (blockIdx.x * 256u + threadIdx.x) >> 5;  // global warp id
    unsigned t  = threadIdx.x & 31u;

    unsigned r0 = wg << 2;          // first of 4 output rows for this warp
    unsigned h  = r0 & 255u;        // multiple of 4; rows stay in one plane
    unsigned nc = r0 >> 8;

    const float4* __restrict__ ib = in + ((size_t)nc << 16) + ((size_t)h << 8);
    float4* __restrict__ ob = out + ((size_t)r0 << 6);

    unsigned t4 = t << 2;
    unsigned o2 = t << 1;

    // ---- rows r0, r0+1 (input rows 2h, 2h+2) ----
    {
        float4 a0, a1, a2, a3, b0, b1, b2, b3;
        ldg256(ib + t4,       a0, a1);
        ldg256(ib + t4 + 2,   a2, a3);
        ldg256(ib + t4 + 256, b0, b1);
        ldg256(ib + t4 + 258, b2, b3);

        stg256(ob + o2,
               a0.x, a0.z, a1.x, a1.z, a2.x, a2.z, a3.x, a3.z);
        stg256(ob + 64 + o2,
               b0.x, b0.z, b1.x, b1.z, b2.x, b2.z, b3.x, b3.z);
    }
    // ---- rows r0+2, r0+3 (input rows 2h+4, 2h+6) ----
    {
        float4 c0, c1, c2, c3, d0, d1, d2, d3;
        ldg256(ib + t4 + 512, c0, c1);
        ldg256(ib + t4 + 514, c2, c3);
        ldg256(ib + t4 + 768, d0, d1);
        ldg256(ib + t4 + 770, d2, d3);

        stg256(ob + 128 + o2,
               c0.x, c0.z, c1.x, c1.z, c2.x, c2.z, c3.x, c3.z);
        stg256(ob + 192 + o2,
               d0.x, d0.z, d1.x, d1.z, d2.x, d2.z, d3.x, d3.z);
    }
}

extern "C" void kernel_launch(void* const* d_in, const int* in_sizes, int n_in,
                              void* d_out, int out_size)
{
    (void)in_sizes; (void)n_in; (void)out_size;
    const float4* in  = (const float4*)d_in[0];
    float4*       out = (float4*)d_out;

    // 262144 output rows / 4 rows per warp = 65536 warps = 8192 blocks of 256
    strided_slice_kernel<<<8192, 256>>>(in, out);
}

// round 9
// speedup vs baseline: 1.0022x; 1.0022x over previous
#include <cuda_runtime.h>
#include <stdint.h>

// StridedSlice: out[n,c,h,w] = x[n,c,2h,2w]
//   in : (8,128,512,512) f32   in row = 128 float4, plane = 65536 float4
//   out: (8,128,256,256) f32   out row = 64 float4, 262144 rows total
//
// R7 shape (best measured) + block-level load/store phase separation.
// One warp -> 2 consecutive output rows. Per row: lane t stores out float4
// [2t,2t+1] via one STG.256 (warp covers the 1 KB row contiguously),
// sourced from in float4 [4t..4t+3] via two LDG.256 at 64 B lane stride.
// A __syncthreads() between the block's load phase (64 KB aggregate) and
// store phase (32 KB) groups DRAM traffic into coarser R/W bursts,
// reducing bus-turnaround overhead at the memory controllers.

__device__ __forceinline__ void ldg256(const float4* __restrict__ p,
                                       float4& v0, float4& v1)
{
    asm("ld.global.v8.f32 {%0,%1,%2,%3,%4,%5,%6,%7}, [%8];"
        : "=f"(v0.x), "=f"(v0.y), "=f"(v0.z), "=f"(v0.w),
          "=f"(v1.x), "=f"(v1.y), "=f"(v1.z), "=f"(v1.w)
        : "l"(p));
}

__device__ __forceinline__ void stg256(float4* __restrict__ p,
                                       float a, float b, float c, float d,
                                       float e, float f, float g, float h)
{
    asm volatile("st.global.v8.f32 [%0], {%1,%2,%3,%4,%5,%6,%7,%8};"
                 :: "l"(p), "f"(a), "f"(b), "f"(c), "f"(d),
                    "f"(e), "f"(f), "f"(g), "f"(h)
                 : "memory");
}

__global__ __launch_bounds__(256) void strided_slice_kernel(
    const float4* __restrict__ in, float4* __restrict__ out)
{
    unsigned wg = (blockIdx.x * 256u + threadIdx.x) >> 5;  // global warp id
    unsigned t  = threadIdx.x & 31u;

    unsigned r0 = wg << 1;          // first of 2 output rows for this warp
    unsigned h  = r0 & 255u;        // even; both rows stay in one plane
    unsigned nc = r0 >> 8;

    const float4* __restrict__ ib = in + ((size_t)nc << 16) + ((size_t)h << 8);
    float4* __restrict__ ob = out + ((size_t)r0 << 6);

    unsigned t4 = t << 2;

    // ---- load phase: 4 front-batched 256-bit loads per thread ----
    float4 a0, a1, a2, a3, b0, b1, b2, b3;
    ldg256(ib + t4,       a0, a1);   // row 2h,   in float4 4t..4t+1
    ldg256(ib + t4 + 2,   a2, a3);   // row 2h,   in float4 4t+2..4t+3
    ldg256(ib + t4 + 256, b0, b1);   // row 2h+2
    ldg256(ib + t4 + 258, b2, b3);

    // group the block's reads before any of its writes hit the LTS/DRAM
    __syncthreads();

    // ---- store phase: 2 fully-coalesced 256-bit stores per thread ----
    stg256(ob + (t << 1),
           a0.x, a0.z, a1.x, a1.z, a2.x, a2.z, a3.x, a3.z);
    stg256(ob + 64 + (t << 1),
           b0.x, b0.z, b1.x, b1.z, b2.x, b2.z, b3.x, b3.z);
}

extern "C" void kernel_launch(void* const* d_in, const int* in_sizes, int n_in,
                              void* d_out, int out_size)
{
    (void)in_sizes; (void)n_in; (void)out_size;
    const float4* in  = (const float4*)d_in[0];
    float4*       out = (float4*)d_out;

    // 262144 output rows / 2 rows per warp = 131072 warps = 16384 blocks of 256
    strided_slice_kernel<<<16384, 256>>>(in, out);
}